// round 15
// baseline (speedup 1.0000x reference)
#include <cuda_runtime.h>
#include <cuda_bf16.h>

// PowerSpectrum: out[n, l*512 + q*16 + p] = cg[l] * sum_m x_nu[l,n,m,q] * x_1[l,n,m,p]
// L=4, M=7, F_NU=32, F_1=16.
//
// Round-15: R12 config (2-tile warp batching, 32-reg/64-warp residency) made
// PERSISTENT with a grid-stride loop (grid = 148*16 CTAs). Removes per-CTA
// launch/prologue overhead and gives free cross-iteration overlap: after a
// warp's STGs for tile-pair i issue, the 6 LDGs for pair i+1 issue immediately,
// so the STS stall starts with loads already in flight (prefetch effect, zero
// extra registers). Lane mapping unchanged: lane j owns p-quad (j&3)*4 and
// q=(j>>2)+8k -> every warp STG.128 is exactly contiguous 512B; x_nu LDS reads
// 4-way-broadcast conflict-free; x_1 LDS.128 conflict-free.

#define PS_L  4
#define PS_M  7
#define PS_FN 32
#define PS_FP 16
#define OUT_PER_N (PS_L * PS_FN * PS_FP)   // 2048
#define F4_PER_TILE 84                     // 56 (x_nu) + 28 (x_1)
#define NSM 148
#define CTAS_PER_SM 16

__global__ __launch_bounds__(128, CTAS_PER_SM)
void ps_kernel(const float* __restrict__ x_nu,
               const float* __restrict__ x_1,
               float* __restrict__ out,
               int N)
{
    __shared__ float4 sm[4 * 2 * F4_PER_TILE];

    const int t = threadIdx.x;
    const int w = t >> 5;                  // warp 0..3 -> l
    const int j = t & 31;                  // lane
    const int l = w;

    const int qb = j >> 2;                 // q = qb + 8k
    const int pq = j & 3;                  // p = pq*4 .. pq*4+3
    const float cgs[PS_L] = {1.0f, 0.57735026918962576f,
                             0.44721359549995794f, 0.37796447300922722f};
    const float cg = cgs[l];

    float4* smA = sm + (w * 2 + 0) * F4_PER_TILE;
    float4* smB = sm + (w * 2 + 1) * F4_PER_TILE;

    const float4* gx_l = reinterpret_cast<const float4*>(x_nu) + (size_t)l * N * 56;
    const float4* g1_l = reinterpret_cast<const float4*>(x_1)  + (size_t)l * N * 28;

    const int half = N >> 1;               // number of tile-pairs
    for (int b = blockIdx.x; b < half; b += gridDim.x) {
        const int n0 = b * 2;              // samples n0, n0+1

        const float4* gxA = gx_l + (size_t)n0 * 56;
        const float4* g1A = g1_l + (size_t)n0 * 28;
        const float4* gxB = gxA + 56;
        const float4* g1B = g1A + 28;

        // ---- issue 6 independent LDGs, STS each as soon as its data arrives ----
        {
            const float4 a0 = gxA[j];
            const float4 a1 = (j < 24) ? gxA[32 + j] : g1A[j - 24];
            float4 a2; if (j < 20) a2 = g1A[8 + j];
            const float4 b0 = gxB[j];
            const float4 b1 = (j < 24) ? gxB[32 + j] : g1B[j - 24];
            float4 b2; if (j < 20) b2 = g1B[8 + j];

            smA[j]      = a0;
            smA[32 + j] = a1;
            if (j < 20) smA[64 + j] = a2;
            smB[j]      = b0;
            smB[32 + j] = b1;
            if (j < 20) smB[64 + j] = b2;
        }
        __syncwarp();

#pragma unroll
        for (int s = 0; s < 2; s++) {
            const float4* smw = (s == 0) ? smA : smB;
            const float*  an  = reinterpret_cast<const float*>(smw);  // [m*32 + q]
            const float4* bp  = smw + 56 + pq;                        // [m*4 + pq]

            float4 acc0 = make_float4(0.f, 0.f, 0.f, 0.f);
            float4 acc1 = acc0, acc2 = acc0, acc3 = acc0;

#pragma unroll
            for (int m = 0; m < PS_M; m++) {
                const float4 b4 = bp[m * 4];
                const float a0 = an[m * PS_FN + qb +  0];
                const float a1 = an[m * PS_FN + qb +  8];
                const float a2 = an[m * PS_FN + qb + 16];
                const float a3 = an[m * PS_FN + qb + 24];

                acc0.x = fmaf(a0, b4.x, acc0.x);
                acc0.y = fmaf(a0, b4.y, acc0.y);
                acc0.z = fmaf(a0, b4.z, acc0.z);
                acc0.w = fmaf(a0, b4.w, acc0.w);
                acc1.x = fmaf(a1, b4.x, acc1.x);
                acc1.y = fmaf(a1, b4.y, acc1.y);
                acc1.z = fmaf(a1, b4.z, acc1.z);
                acc1.w = fmaf(a1, b4.w, acc1.w);
                acc2.x = fmaf(a2, b4.x, acc2.x);
                acc2.y = fmaf(a2, b4.y, acc2.y);
                acc2.z = fmaf(a2, b4.z, acc2.z);
                acc2.w = fmaf(a2, b4.w, acc2.w);
                acc3.x = fmaf(a3, b4.x, acc3.x);
                acc3.y = fmaf(a3, b4.y, acc3.y);
                acc3.z = fmaf(a3, b4.z, acc3.z);
                acc3.w = fmaf(a3, b4.w, acc3.w);
            }

            acc0.x *= cg; acc0.y *= cg; acc0.z *= cg; acc0.w *= cg;
            acc1.x *= cg; acc1.y *= cg; acc1.z *= cg; acc1.w *= cg;
            acc2.x *= cg; acc2.y *= cg; acc2.z *= cg; acc2.w *= cg;
            acc3.x *= cg; acc3.y *= cg; acc3.z *= cg; acc3.w *= cg;

            float4* o = reinterpret_cast<float4*>(
                out + (size_t)(n0 + s) * OUT_PER_N + l * (PS_FN * PS_FP));
            o[j +  0] = acc0;
            o[j + 32] = acc1;
            o[j + 64] = acc2;
            o[j + 96] = acc3;
        }

        // guard smem reuse across grid-stride iterations
        __syncwarp();
    }
}

extern "C" void kernel_launch(void* const* d_in, const int* in_sizes, int n_in,
                              void* d_out, int out_size)
{
    const float* x_nu = (const float*)d_in[0];
    const float* x_1  = (const float*)d_in[1];
    float* out = (float*)d_out;

    const int N = in_sizes[0] / (PS_L * PS_M * PS_FN);

    int grid = NSM * CTAS_PER_SM;          // fully-resident persistent wave
    if (grid > N / 2) grid = N / 2;

    ps_kernel<<<grid, 128>>>(x_nu, x_1, out, N);
}

// round 16
// speedup vs baseline: 1.2253x; 1.2253x over previous
#include <cuda_runtime.h>
#include <cuda_bf16.h>

// PowerSpectrum: out[n, l*512 + q*16 + p] = cg[l] * sum_m x_nu[l,n,m,q] * x_1[l,n,m,p]
// L=4, M=7, F_NU=32, F_1=16.
//
// FINAL — best scored configuration over a 15-round exploration (104.5us wall).
// One-shot CTA per 2 samples; warp w owns l=w and samples {2b, 2b+1}:
// 6 independent front-batched LDG.128 (both tiles) -> immediate STS (staging
// regs die at once) -> one __syncwarp -> compute + store tile A then tile B.
// __launch_bounds__(128,16) pins 32 registers -> 64 warps/SM resident.
// Lane mapping: lane j owns p-quad (j&3)*4 and q=(j>>2)+8k, k=0..3 — every warp
// STG.128 is exactly contiguous 512B (minimal store wavefronts); x_nu LDS reads
// are 4-way-broadcast conflict-free; x_1 LDS.128 conflict-free.
//
// Exploration summary (all plateaued at 6.2-6.4 TB/s = mixed R/W DRAM ceiling
// for the irreducible 678 MB stream): cp.async pipelines (issue-floor +
// wait_group overhead lost), register prefetch (occupancy lost), direct
// sector-perfect LDG (MLP collapse), L2 prefetch at 1-wave (L2 eviction,
// +120MB re-reads) and 1/4-wave (neutral), streaming cache hints (neutral/neg),
// persistence x3 (loop-carried serialization beats HW CTA-launch overlap).

#define PS_L  4
#define PS_M  7
#define PS_FN 32
#define PS_FP 16
#define OUT_PER_N (PS_L * PS_FN * PS_FP)   // 2048
#define F4_PER_TILE 84                     // 56 (x_nu) + 28 (x_1)

__global__ __launch_bounds__(128, 16)
void ps_kernel(const float* __restrict__ x_nu,
               const float* __restrict__ x_1,
               float* __restrict__ out,
               int N)
{
    __shared__ float4 sm[4 * 2 * F4_PER_TILE];

    const int t = threadIdx.x;
    const int w = t >> 5;                  // warp 0..3 -> l
    const int j = t & 31;                  // lane
    const int l = w;
    const int n0 = blockIdx.x * 2;         // samples n0, n0+1

    const float4* gxA = reinterpret_cast<const float4*>(x_nu) + ((size_t)l * N + n0) * 56;
    const float4* g1A = reinterpret_cast<const float4*>(x_1)  + ((size_t)l * N + n0) * 28;
    const float4* gxB = gxA + 56;
    const float4* g1B = g1A + 28;

    float4* smA = sm + (w * 2 + 0) * F4_PER_TILE;
    float4* smB = sm + (w * 2 + 1) * F4_PER_TILE;

    // ---- issue 6 independent LDGs, STS each as soon as its data arrives ----
    {
        const float4 a0 = gxA[j];
        const float4 a1 = (j < 24) ? gxA[32 + j] : g1A[j - 24];
        float4 a2; if (j < 20) a2 = g1A[8 + j];
        const float4 b0 = gxB[j];
        const float4 b1 = (j < 24) ? gxB[32 + j] : g1B[j - 24];
        float4 b2; if (j < 20) b2 = g1B[8 + j];

        smA[j]      = a0;
        smA[32 + j] = a1;
        if (j < 20) smA[64 + j] = a2;
        smB[j]      = b0;
        smB[32 + j] = b1;
        if (j < 20) smB[64 + j] = b2;
    }
    __syncwarp();

    const int qb = j >> 2;                 // q = qb + 8k
    const int pq = j & 3;                  // p = pq*4 .. pq*4+3
    const float cgs[PS_L] = {1.0f, 0.57735026918962576f,
                             0.44721359549995794f, 0.37796447300922722f};
    const float cg = cgs[l];

#pragma unroll
    for (int s = 0; s < 2; s++) {
        const float4* smw = (s == 0) ? smA : smB;
        const float*  an  = reinterpret_cast<const float*>(smw);   // [m*32 + q]
        const float4* bp  = smw + 56 + pq;                         // [m*4 + pq]

        float4 acc0 = make_float4(0.f, 0.f, 0.f, 0.f);
        float4 acc1 = acc0, acc2 = acc0, acc3 = acc0;

#pragma unroll
        for (int m = 0; m < PS_M; m++) {
            const float4 b = bp[m * 4];
            const float a0 = an[m * PS_FN + qb +  0];
            const float a1 = an[m * PS_FN + qb +  8];
            const float a2 = an[m * PS_FN + qb + 16];
            const float a3 = an[m * PS_FN + qb + 24];

            acc0.x = fmaf(a0, b.x, acc0.x);
            acc0.y = fmaf(a0, b.y, acc0.y);
            acc0.z = fmaf(a0, b.z, acc0.z);
            acc0.w = fmaf(a0, b.w, acc0.w);
            acc1.x = fmaf(a1, b.x, acc1.x);
            acc1.y = fmaf(a1, b.y, acc1.y);
            acc1.z = fmaf(a1, b.z, acc1.z);
            acc1.w = fmaf(a1, b.w, acc1.w);
            acc2.x = fmaf(a2, b.x, acc2.x);
            acc2.y = fmaf(a2, b.y, acc2.y);
            acc2.z = fmaf(a2, b.z, acc2.z);
            acc2.w = fmaf(a2, b.w, acc2.w);
            acc3.x = fmaf(a3, b.x, acc3.x);
            acc3.y = fmaf(a3, b.y, acc3.y);
            acc3.z = fmaf(a3, b.z, acc3.z);
            acc3.w = fmaf(a3, b.w, acc3.w);
        }

        acc0.x *= cg; acc0.y *= cg; acc0.z *= cg; acc0.w *= cg;
        acc1.x *= cg; acc1.y *= cg; acc1.z *= cg; acc1.w *= cg;
        acc2.x *= cg; acc2.y *= cg; acc2.z *= cg; acc2.w *= cg;
        acc3.x *= cg; acc3.y *= cg; acc3.z *= cg; acc3.w *= cg;

        float4* o = reinterpret_cast<float4*>(
            out + (size_t)(n0 + s) * OUT_PER_N + l * (PS_FN * PS_FP));
        o[j +  0] = acc0;
        o[j + 32] = acc1;
        o[j + 64] = acc2;
        o[j + 96] = acc3;
    }
}

extern "C" void kernel_launch(void* const* d_in, const int* in_sizes, int n_in,
                              void* d_out, int out_size)
{
    const float* x_nu = (const float*)d_in[0];
    const float* x_1  = (const float*)d_in[1];
    float* out = (float*)d_out;

    const int N = in_sizes[0] / (PS_L * PS_M * PS_FN);

    ps_kernel<<<N / 2, 128>>>(x_nu, x_1, out, N);
}